// round 8
// baseline (speedup 1.0000x reference)
#include <cuda_runtime.h>
#include <cuda_fp16.h>

static constexpr int NCOLS = 99;
static constexpr int TPB   = 128;   // threads per block
static constexpr int TILE  = 64;    // rows per tile (2 threads per row in LSE)
static constexpr int NPREP = 296;   // prep-role CTAs (first in grid)
static constexpr int GRID  = 1184;  // 8 CTAs/SM x 148 SMs -> single resident wave

// ---------------- device scratch (single memset(0), no allocation) ---------
struct Zeros {
    double   acc[3];        // [0]=mse sum, [1]=dot sum, [2]=lse sum
    unsigned hist[200];     // [sex(2)][feat(10)][bin(10)]
    unsigned maxkey[10];    // atomicMax of key(x)
    unsigned cominkey[10];  // atomicMax of ~key(x)
    unsigned done[3];       // [0] prep minmax sync, [1] finalize ticket, [2] prep hist done
    unsigned ticket;        // dynamic tile ticket
};
__device__ Zeros gz;

// monotonic float<->uint key
__device__ __forceinline__ unsigned f2key(float f) {
    unsigned u = __float_as_uint(f);
    return (u & 0x80000000u) ? ~u : (u | 0x80000000u);
}
__device__ __forceinline__ float key2f(unsigned k) {
    unsigned u = (k & 0x80000000u) ? (k ^ 0x80000000u) : ~k;
    return __uint_as_float(u);
}

// ---------------- helpers ---------------------------------------------------
__device__ __forceinline__ bool quad_rare(int c0) {
    return (c0 == 0) | ((unsigned)(c0 - 52) <= 5u) | (c0 >= 96);
}
__device__ __forceinline__ int wrap99(int c) { return (c >= NCOLS) ? c - NCOLS : c; }

// consume one float4-pair: fp16 store + dotAll FFMAs + rare cont-col fixup
__device__ __forceinline__ void consume(
    float4 d, float4 t, int c0, __half* smh, int i,
    float& dot0, float& dot1, float& mse, float& dotc)
{
    union { __half2 h[2]; uint2 u; } pk;
    pk.h[0] = __floats2half2_rn(d.x, d.y);
    pk.h[1] = __floats2half2_rn(d.z, d.w);
    *reinterpret_cast<uint2*>(smh + 4 * i) = pk.u;   // 8B aligned
    dot0 = fmaf(d.x, t.x, dot0);
    dot1 = fmaf(d.y, t.y, dot1);
    dot0 = fmaf(d.z, t.z, dot0);
    dot1 = fmaf(d.w, t.w, dot1);
    if (quad_rare(c0)) {
        float dv[4] = {d.x, d.y, d.z, d.w};
        float tv[4] = {t.x, t.y, t.z, t.w};
        int c = c0;
#pragma unroll
        for (int j = 0; j < 4; j++) {
            bool cont = (c == 0) | ((unsigned)(c - 55) <= 2u);
            if (cont) {
                float df = dv[j] - tv[j];
                mse  = fmaf(df, df, mse);
                dotc = fmaf(dv[j], tv[j], dotc);   // subtract later
            }
            if (++c == NCOLS) c = 0;
        }
    }
}

// one LSE column step (guarded state machine)
// even half: cols 1..44, flush after {7,23,30,44}, lend=45
// odd  half: cols 45..98, flush after {50,52,54,98}, skip 55..57, lend=99
__device__ __forceinline__ void lse_step(
    const __half* rowp, int& li, int lend,
    unsigned long long mask, float& s, float& acc)
{
    if (li < lend) {
        s += __expf(__half2float(rowp[li]));
        bool fl = (li < 64) ? (((mask >> li) & 1ull) != 0ull) : (li == 98);
        if (fl) {
            acc += __logf(s);
            s = 0.f;
            li = (li == 54) ? 58 : li + 1;
        } else {
            li++;
        }
    }
}

// ---------------- fused persistent kernel ----------------------------------
__global__ void __launch_bounds__(TPB, 8)
k_fused(const float4* __restrict__ e4,
        const float* __restrict__ dec, const float* __restrict__ tru,
        float* __restrict__ out, int B) {
    __shared__ __half buf[2][TILE * NCOLS];    // 2 x 12672 B
    __shared__ float wr[3][TPB / 32];
    __shared__ int   s_next, s_last;
    __shared__ float s_mn[4][10], s_mx[4][10]; // prep role
    __shared__ unsigned sh[200];
    __shared__ float smn[10], swid[10];

    const int t = threadIdx.x, lane = t & 31, w = t >> 5;

    if (blockIdx.x < NPREP) {
        // ================= PREP ROLE (then joins tile work) =================
        const int stride = NPREP * TPB;
        const int gbase  = blockIdx.x * TPB + t;

        float mn[10], mx[10];
        const float INF = __int_as_float(0x7f800000);
#pragma unroll
        for (int i = 0; i < 10; i++) { mn[i] = INF; mx[i] = -INF; }
        for (int r = gbase; r < B; r += 2 * stride) {
            float4 a0 = e4[3*r], b0 = e4[3*r+1], c0 = e4[3*r+2];
            int r1 = r + stride;
            bool ok1 = r1 < B;
            float4 a1, b1, c1;
            if (ok1) { a1 = e4[3*r1]; b1 = e4[3*r1+1]; c1 = e4[3*r1+2]; }
            float v0[10] = {a0.x,a0.y,a0.z,a0.w,b0.x,b0.y,b0.z,b0.w,c0.x,c0.y};
#pragma unroll
            for (int i = 0; i < 10; i++) {
                mn[i] = fminf(mn[i], v0[i]);
                mx[i] = fmaxf(mx[i], v0[i]);
            }
            if (ok1) {
                float v1[10] = {a1.x,a1.y,a1.z,a1.w,b1.x,b1.y,b1.z,b1.w,c1.x,c1.y};
#pragma unroll
                for (int i = 0; i < 10; i++) {
                    mn[i] = fminf(mn[i], v1[i]);
                    mx[i] = fmaxf(mx[i], v1[i]);
                }
            }
        }
#pragma unroll
        for (int i = 0; i < 10; i++) {
#pragma unroll
            for (int o = 16; o > 0; o >>= 1) {
                mn[i] = fminf(mn[i], __shfl_xor_sync(0xFFFFFFFFu, mn[i], o));
                mx[i] = fmaxf(mx[i], __shfl_xor_sync(0xFFFFFFFFu, mx[i], o));
            }
        }
        if (lane == 0) {
#pragma unroll
            for (int i = 0; i < 10; i++) { s_mn[w][i] = mn[i]; s_mx[w][i] = mx[i]; }
        }
        for (int j = t; j < 200; j += TPB) sh[j] = 0u;
        __syncthreads();
        if (t < 10) {
            float m = s_mn[0][t], x = s_mx[0][t];
#pragma unroll
            for (int ww = 1; ww < 4; ww++) { m = fminf(m, s_mn[ww][t]); x = fmaxf(x, s_mx[ww][t]); }
            atomicMax(&gz.cominkey[t], ~f2key(m));
            atomicMax(&gz.maxkey[t],    f2key(x));
        }

        __threadfence();
        __syncthreads();
        if (t == 0) {
            atomicAdd(&gz.done[0], 1u);
            while (atomicAdd(&gz.done[0], 0u) < (unsigned)NPREP) __nanosleep(64);
        }
        __syncthreads();
        __threadfence();

        if (t < 10) {
            float m = key2f(~gz.cominkey[t]);
            float x = key2f( gz.maxkey[t]);
            smn[t]  = m;
            swid[t] = fmaxf(x - m, 1e-12f);
        }
        __syncthreads();

        const int B_al = B & ~31;
        for (int r = gbase; r < B_al; r += stride) {
            float4 a = e4[3*r], b = e4[3*r+1], c = e4[3*r+2];
            unsigned base = (c.w == 0.0f) ? 0u : 100u;   // col 11 = sex
            float v[10] = {a.x,a.y,a.z,a.w,b.x,b.y,b.z,b.w,c.x,c.y};
#pragma unroll
            for (int i = 0; i < 10; i++) {
                float tt = (v[i] - smn[i]) / swid[i] * 10.0f;
                int bi = (int)floorf(tt);
                bi = bi < 0 ? 0 : (bi > 9 ? 9 : bi);
                unsigned key = base + (unsigned)(i * 10 + bi);
                unsigned msk = __match_any_sync(0xFFFFFFFFu, key);
                if ((msk & ((1u << lane) - 1u)) == 0u)
                    atomicAdd(&sh[key], (unsigned)__popc(msk));
            }
        }
        for (int r = B_al + gbase; r < B; r += stride) {
            float4 a = e4[3*r], b = e4[3*r+1], c = e4[3*r+2];
            unsigned base = (c.w == 0.0f) ? 0u : 100u;
            float v[10] = {a.x,a.y,a.z,a.w,b.x,b.y,b.z,b.w,c.x,c.y};
#pragma unroll
            for (int i = 0; i < 10; i++) {
                float tt = (v[i] - smn[i]) / swid[i] * 10.0f;
                int bi = (int)floorf(tt);
                bi = bi < 0 ? 0 : (bi > 9 ? 9 : bi);
                atomicAdd(&sh[base + (unsigned)(i * 10 + bi)], 1u);
            }
        }
        __syncthreads();
        for (int j = t; j < 200; j += TPB)
            if (sh[j]) atomicAdd(&gz.hist[j], sh[j]);
        __threadfence();
        __syncthreads();
        if (t == 0) atomicAdd(&gz.done[2], 1u);   // hist ticket
        // fall through to tile work
    }

    // ================= TILE PIPELINE (all CTAs) =================
    const int NT = (B + TILE - 1) / TILE;
    float dot0 = 0.f, dot1 = 0.f, a_mse = 0.f, dotc = 0.f, a_lse = 0.f;

    const int cst   = (4 * t) % NCOLS;     // col of first element of pair j=0
    const int half_ = t & 1;
    const int myrow = t >> 1;
    const unsigned long long lmask = half_
        ? ((1ull << 50) | (1ull << 52) | (1ull << 54))
        : ((1ull << 7) | (1ull << 23) | (1ull << 30) | (1ull << 44));
    const int lstart = half_ ? 45 : 1;
    const int lend   = half_ ? 99 : 45;

    if (t == 0) s_next = (int)atomicAdd(&gz.ticket, 1u);
    __syncthreads();
    int  tile = s_next;
    bool have = tile < NT;
    int  cur  = 0;
    int  rows_cur = 0;

    if (have) {
        // pipeline fill: plain P1 of first tile into buf[0]
        rows_cur = min(TILE, B - tile * TILE);
        const int nflt = rows_cur * NCOLS, n4 = nflt >> 2;
        const size_t eb = (size_t)tile * TILE * NCOLS;
        const float4* d4 = (const float4*)(dec + eb);
        const float4* t4 = (const float4*)(tru + eb);
        int c = cst;
        for (int i = t; i < n4; i += TPB) {
            consume(d4[i], t4[i], c, buf[0], i, dot0, dot1, a_mse, dotc);
            c = wrap99(c + 17);
        }
        for (int e = (n4 << 2) + t; e < nflt; e += TPB) {
            float d = dec[eb + e], tt = tru[eb + e];
            buf[0][e] = __float2half_rn(d);
            int cc = e % NCOLS;
            bool cont = (cc == 0) | ((unsigned)(cc - 55) <= 2u);
            dot0 = fmaf(d, tt, dot0);
            if (cont) { float df = d - tt; a_mse = fmaf(df, df, a_mse); dotc = fmaf(d, tt, dotc); }
        }
    }

    while (have) {
        if (t == 0) s_next = (int)atomicAdd(&gz.ticket, 1u);
        __syncthreads();   // publishes ticket; orders prior stores before LSE reads
        const int  ntile    = s_next;
        const bool havenext = ntile < NT;

        // LSE state for current buffer
        int   li = (myrow < rows_cur) ? lstart : lend;
        float s  = 0.f;
        const __half* rowp = buf[cur] + myrow * NCOLS;

        if (havenext) {
            // merged: stream next tile into buf[cur^1] while doing LSE(buf[cur])
            const int nrows = min(TILE, B - ntile * TILE);
            const int nflt = nrows * NCOLS, n4 = nflt >> 2;
            const size_t eb = (size_t)ntile * TILE * NCOLS;
            const float4* d4 = (const float4*)(dec + eb);
            const float4* t4 = (const float4*)(tru + eb);
            __half* bo = buf[cur ^ 1];
            int c = cst;

            int i = t;
            bool v = i < n4;
            float4 dd, tt;
            if (v) { dd = d4[i]; tt = t4[i]; }
            const int NIT = (n4 + TPB - 1) / TPB;
            for (int j = 0; j < NIT; j++) {
                const int inext = i + TPB;
                const bool vn = inext < n4;
                float4 nd, nt2;
                if (vn) { nd = d4[inext]; nt2 = t4[inext]; }
                // 4 LSE columns between load and consume (covers latency + MUFU)
                lse_step(rowp, li, lend, lmask, s, a_lse);
                lse_step(rowp, li, lend, lmask, s, a_lse);
                lse_step(rowp, li, lend, lmask, s, a_lse);
                lse_step(rowp, li, lend, lmask, s, a_lse);
                if (v) consume(dd, tt, c, bo, i, dot0, dot1, a_mse, dotc);
                c = wrap99(c + 17);
                dd = nd; tt = nt2; i = inext; v = vn;
            }
            for (int e = (n4 << 2) + t; e < nflt; e += TPB) {   // scalar tail
                float d = dec[eb + e], tt2 = tru[eb + e];
                bo[e] = __float2half_rn(d);
                int cc = e % NCOLS;
                bool cont = (cc == 0) | ((unsigned)(cc - 55) <= 2u);
                dot0 = fmaf(d, tt2, dot0);
                if (cont) { float df = d - tt2; a_mse = fmaf(df, df, a_mse); dotc = fmaf(d, tt2, dotc); }
            }
        }
        // drain remaining LSE columns of current buffer
        while (li < lend) lse_step(rowp, li, lend, lmask, s, a_lse);

        cur ^= 1;
        tile = ntile;
        have = havenext;
        if (havenext) rows_cur = min(TILE, B - ntile * TILE);
    }

    // ---- block reduce -> double global atomics ----
    float a_dot = (dot0 + dot1) - dotc;
#pragma unroll
    for (int o = 16; o > 0; o >>= 1) {
        a_mse += __shfl_xor_sync(0xFFFFFFFFu, a_mse, o);
        a_dot += __shfl_xor_sync(0xFFFFFFFFu, a_dot, o);
        a_lse += __shfl_xor_sync(0xFFFFFFFFu, a_lse, o);
    }
    if (lane == 0) { wr[0][w] = a_mse; wr[1][w] = a_dot; wr[2][w] = a_lse; }
    __syncthreads();
    if (t == 0) {
        float m = 0.f, d = 0.f, l = 0.f;
#pragma unroll
        for (int k = 0; k < TPB / 32; k++) { m += wr[0][k]; d += wr[1][k]; l += wr[2][k]; }
        atomicAdd(&gz.acc[0], (double)m);
        atomicAdd(&gz.acc[1], (double)d);
        atomicAdd(&gz.acc[2], (double)l);
        __threadfence();
        unsigned tk = atomicAdd(&gz.done[1], 1u);
        s_last = (tk == gridDim.x - 1u) ? 1 : 0;
        if (s_last) {   // wait for prep histogram tickets
            while (atomicAdd(&gz.done[2], 0u) < (unsigned)NPREP) __nanosleep(64);
        }
    }
    __syncthreads();

    // ---- last CTA finalizes (double precision, 32 lanes) ----
    if (s_last && t < 32) {
        __threadfence();
        int lane32 = t;
        double mcnt = (lane32 < 10) ? (double)gz.hist[lane32]       : 0.0;
        double fcnt = (lane32 < 10) ? (double)gz.hist[100 + lane32] : 0.0;
#pragma unroll
        for (int o = 16; o > 0; o >>= 1) {
            mcnt += __shfl_xor_sync(0xFFFFFFFFu, mcnt, o);
            fcnt += __shfl_xor_sync(0xFFFFFFFFu, fcnt, o);
        }
        double mc = fmax(mcnt, 1.0), fc = fmax(fcnt, 1.0);
        double kld = 0.0;
#pragma unroll
        for (int k = 0; k < 4; k++) {
            int b = k * 32 + lane32;
            if (b < 100) {
                double p = (double)gz.hist[b] / mc;
                double q = (double)gz.hist[100 + b] / fc;
                if (p > 0.0 && q > 0.0) kld += p * log(p / q);
            }
        }
#pragma unroll
        for (int o = 16; o > 0; o >>= 1)
            kld += __shfl_xor_sync(0xFFFFFFFFu, kld, o);
        if (lane32 == 0) {
            double mseS = atomicAdd(&gz.acc[0], 0.0);
            double dotS = atomicAdd(&gz.acc[1], 0.0);
            double lseS = atomicAdd(&gz.acc[2], 0.0);
            double fB   = (double)B;
            double mse  = mseS / fB;
            double ce   = (lseS - dotS) / fB;
            double akld = 0.5 * kld;
            out[0] = (float)(0.5 * (mse + ce) + akld);
            out[1] = (float)mse;
            out[2] = (float)ce;
            out[3] = (float)akld;
        }
    }
}

// ---------------- launcher ----------------
extern "C" void kernel_launch(void* const* d_in, const int* in_sizes, int n_in,
                              void* d_out, int out_size) {
    const float* enc = (const float*)d_in[0];   // [B,12]
    const float* dec = (const float*)d_in[1];   // [B,99]
    const float* tru = (const float*)d_in[2];   // [B,99]
    const int B = in_sizes[1] / NCOLS;
    float* out = (float*)d_out;

    void* pz = nullptr;
    cudaGetSymbolAddress(&pz, gz);
    cudaMemsetAsync(pz, 0, sizeof(Zeros), 0);

    cudaFuncSetAttribute(k_fused, cudaFuncAttributePreferredSharedMemoryCarveout, 100);

    k_fused<<<GRID, TPB>>>((const float4*)enc, dec, tru, out, B);
}

// round 9
// speedup vs baseline: 1.0008x; 1.0008x over previous
#include <cuda_runtime.h>
#include <cuda_fp16.h>

static constexpr int NCOLS = 99;
static constexpr int TPB   = 128;   // 2 producer warps + 2 consumer warps
static constexpr int TILE  = 64;    // rows per tile (one consumer thread per row)
static constexpr int NPREP = 296;   // prep-role CTAs (first in grid)
static constexpr int GRID  = 1184;  // 8 CTAs/SM x 148 SMs, persistent

// ---------------- device scratch (single memset(0), no allocation) ---------
struct Zeros {
    double   acc[3];        // [0]=mse sum, [1]=dot sum, [2]=lse sum
    unsigned hist[200];     // [sex(2)][feat(10)][bin(10)]
    unsigned maxkey[10];    // atomicMax of key(x)
    unsigned cominkey[10];  // atomicMax of ~key(x)
    unsigned done[3];       // [0] prep minmax sync, [1] finalize ticket, [2] prep hist done
    unsigned ticket;        // dynamic tile ticket
};
__device__ Zeros gz;

// monotonic float<->uint key
__device__ __forceinline__ unsigned f2key(float f) {
    unsigned u = __float_as_uint(f);
    return (u & 0x80000000u) ? ~u : (u | 0x80000000u);
}
__device__ __forceinline__ float key2f(unsigned k) {
    unsigned u = (k & 0x80000000u) ? (k ^ 0x80000000u) : ~k;
    return __uint_as_float(u);
}

// ---------------- helpers ---------------------------------------------------
template <int S, int E>
__device__ __forceinline__ float lse_blk_h(const __half* row) {
    float s = 0.f;
#pragma unroll
    for (int c = S; c < E; ++c) s += __expf(__half2float(row[c]));
    return __logf(s);
}

__device__ __forceinline__ bool quad_rare(int c0) {
    return (c0 == 0) | ((unsigned)(c0 - 52) <= 5u) | (c0 >= 96);
}
__device__ __forceinline__ int wrap99(int c) { return (c >= NCOLS) ? c - NCOLS : c; }

// consume one float4-pair: fp16 store + dotAll FFMAs + rare cont-col fixup
__device__ __forceinline__ void consume(
    float4 d, float4 t, int c0, __half* smh, int i,
    float& dot0, float& dot1, float& mse, float& dotc)
{
    union { __half2 h[2]; uint2 u; } pk;
    pk.h[0] = __floats2half2_rn(d.x, d.y);
    pk.h[1] = __floats2half2_rn(d.z, d.w);
    *reinterpret_cast<uint2*>(smh + 4 * i) = pk.u;   // 8B aligned
    dot0 = fmaf(d.x, t.x, dot0);
    dot1 = fmaf(d.y, t.y, dot1);
    dot0 = fmaf(d.z, t.z, dot0);
    dot1 = fmaf(d.w, t.w, dot1);
    if (quad_rare(c0)) {
        float dv[4] = {d.x, d.y, d.z, d.w};
        float tv[4] = {t.x, t.y, t.z, t.w};
        int c = c0;
#pragma unroll
        for (int j = 0; j < 4; j++) {
            bool cont = (c == 0) | ((unsigned)(c - 55) <= 2u);
            if (cont) {
                float df = dv[j] - tv[j];
                mse  = fmaf(df, df, mse);
                dotc = fmaf(dv[j], tv[j], dotc);   // subtract later
            }
            if (++c == NCOLS) c = 0;
        }
    }
}

// ---------------- fused persistent kernel ----------------------------------
__global__ void __launch_bounds__(TPB, 8)
k_fused(const float4* __restrict__ e4,
        const float* __restrict__ dec, const float* __restrict__ tru,
        float* __restrict__ out, int B) {
    __shared__ __half buf[2][TILE * NCOLS];    // 2 x 12672 B
    __shared__ int   s_tile[2];
    __shared__ float wr[3][TPB / 32];
    __shared__ int   s_last;
    __shared__ float s_mn[4][10], s_mx[4][10]; // prep role
    __shared__ unsigned sh[200];
    __shared__ float smn[10], swid[10];

    const int t = threadIdx.x, lane = t & 31, w = t >> 5;

    if (blockIdx.x < NPREP) {
        // ================= PREP ROLE (then joins tile work) =================
        const int stride = NPREP * TPB;
        const int gbase  = blockIdx.x * TPB + t;

        float mn[10], mx[10];
        const float INF = __int_as_float(0x7f800000);
#pragma unroll
        for (int i = 0; i < 10; i++) { mn[i] = INF; mx[i] = -INF; }
        for (int r = gbase; r < B; r += 2 * stride) {
            float4 a0 = e4[3*r], b0 = e4[3*r+1], c0 = e4[3*r+2];
            int r1 = r + stride;
            bool ok1 = r1 < B;
            float4 a1, b1, c1;
            if (ok1) { a1 = e4[3*r1]; b1 = e4[3*r1+1]; c1 = e4[3*r1+2]; }
            float v0[10] = {a0.x,a0.y,a0.z,a0.w,b0.x,b0.y,b0.z,b0.w,c0.x,c0.y};
#pragma unroll
            for (int i = 0; i < 10; i++) {
                mn[i] = fminf(mn[i], v0[i]);
                mx[i] = fmaxf(mx[i], v0[i]);
            }
            if (ok1) {
                float v1[10] = {a1.x,a1.y,a1.z,a1.w,b1.x,b1.y,b1.z,b1.w,c1.x,c1.y};
#pragma unroll
                for (int i = 0; i < 10; i++) {
                    mn[i] = fminf(mn[i], v1[i]);
                    mx[i] = fmaxf(mx[i], v1[i]);
                }
            }
        }
#pragma unroll
        for (int i = 0; i < 10; i++) {
#pragma unroll
            for (int o = 16; o > 0; o >>= 1) {
                mn[i] = fminf(mn[i], __shfl_xor_sync(0xFFFFFFFFu, mn[i], o));
                mx[i] = fmaxf(mx[i], __shfl_xor_sync(0xFFFFFFFFu, mx[i], o));
            }
        }
        if (lane == 0) {
#pragma unroll
            for (int i = 0; i < 10; i++) { s_mn[w][i] = mn[i]; s_mx[w][i] = mx[i]; }
        }
        for (int j = t; j < 200; j += TPB) sh[j] = 0u;
        __syncthreads();
        if (t < 10) {
            float m = s_mn[0][t], x = s_mx[0][t];
#pragma unroll
            for (int ww = 1; ww < 4; ww++) { m = fminf(m, s_mn[ww][t]); x = fmaxf(x, s_mx[ww][t]); }
            atomicMax(&gz.cominkey[t], ~f2key(m));
            atomicMax(&gz.maxkey[t],    f2key(x));
        }

        __threadfence();
        __syncthreads();
        if (t == 0) {
            atomicAdd(&gz.done[0], 1u);
            while (atomicAdd(&gz.done[0], 0u) < (unsigned)NPREP) __nanosleep(64);
        }
        __syncthreads();
        __threadfence();

        if (t < 10) {
            float m = key2f(~gz.cominkey[t]);
            float x = key2f( gz.maxkey[t]);
            smn[t]  = m;
            swid[t] = fmaxf(x - m, 1e-12f);
        }
        __syncthreads();

        const int B_al = B & ~31;
        for (int r = gbase; r < B_al; r += stride) {
            float4 a = e4[3*r], b = e4[3*r+1], c = e4[3*r+2];
            unsigned base = (c.w == 0.0f) ? 0u : 100u;   // col 11 = sex
            float v[10] = {a.x,a.y,a.z,a.w,b.x,b.y,b.z,b.w,c.x,c.y};
#pragma unroll
            for (int i = 0; i < 10; i++) {
                float tt = (v[i] - smn[i]) / swid[i] * 10.0f;
                int bi = (int)floorf(tt);
                bi = bi < 0 ? 0 : (bi > 9 ? 9 : bi);
                unsigned key = base + (unsigned)(i * 10 + bi);
                unsigned msk = __match_any_sync(0xFFFFFFFFu, key);
                if ((msk & ((1u << lane) - 1u)) == 0u)
                    atomicAdd(&sh[key], (unsigned)__popc(msk));
            }
        }
        for (int r = B_al + gbase; r < B; r += stride) {
            float4 a = e4[3*r], b = e4[3*r+1], c = e4[3*r+2];
            unsigned base = (c.w == 0.0f) ? 0u : 100u;
            float v[10] = {a.x,a.y,a.z,a.w,b.x,b.y,b.z,b.w,c.x,c.y};
#pragma unroll
            for (int i = 0; i < 10; i++) {
                float tt = (v[i] - smn[i]) / swid[i] * 10.0f;
                int bi = (int)floorf(tt);
                bi = bi < 0 ? 0 : (bi > 9 ? 9 : bi);
                atomicAdd(&sh[base + (unsigned)(i * 10 + bi)], 1u);
            }
        }
        __syncthreads();
        for (int j = t; j < 200; j += TPB)
            if (sh[j]) atomicAdd(&gz.hist[j], sh[j]);
        __threadfence();
        __syncthreads();
        if (t == 0) atomicAdd(&gz.done[2], 1u);   // hist ticket
        // fall through to tile pipeline
    }

    // ========== TILE PIPELINE: producer warps 0-1, consumer warps 2-3 ======
    const int NT = (B + TILE - 1) / TILE;
    float dot0 = 0.f, dot1 = 0.f, a_mse = 0.f, dotc = 0.f, a_lse = 0.f;
    const bool isProd = t < 64;
    const int  myrow  = t - 64;                 // consumer row (0..63)

    if (t == 0) s_tile[0] = (int)atomicAdd(&gz.ticket, 1u);
    __syncthreads();

    int p = 0;
    while (true) {
        const int T = s_tile[p];                // copied to register pre-barrier
        if (T >= NT) break;
        if (t == 0) s_tile[p ^ 1] = (int)atomicAdd(&gz.ticket, 1u);
        const int rows = min(TILE, B - T * TILE);

        if (isProd) {
            // ---- stream tile T into buf[p], accumulate dot/mse ----
            const int nflt = rows * NCOLS, n4 = nflt >> 2;
            const size_t eb = (size_t)T * TILE * NCOLS;
            const float4* d4 = (const float4*)(dec + eb);
            const float4* t4 = (const float4*)(tru + eb);
            __half* bo = buf[p];

            int i = t, c = (4 * t) % NCOLS;     // step 64 float4 = +58 mod 99
            while (i + 64 < n4) {
                float4 dA = d4[i], tA = t4[i], dB = d4[i + 64], tB = t4[i + 64];
                consume(dA, tA, c, bo, i, dot0, dot1, a_mse, dotc);
                int c2 = wrap99(c + 58);
                consume(dB, tB, c2, bo, i + 64, dot0, dot1, a_mse, dotc);
                c = wrap99(c2 + 58);
                i += 128;
            }
            if (i < n4) consume(d4[i], t4[i], c, bo, i, dot0, dot1, a_mse, dotc);
            for (int e = (n4 << 2) + t; e < nflt; e += 64) {   // scalar tail
                float d = dec[eb + e], tt = tru[eb + e];
                bo[e] = __float2half_rn(d);
                int cc = e % NCOLS;
                bool cont = (cc == 0) | ((unsigned)(cc - 55) <= 2u);
                dot0 = fmaf(d, tt, dot0);
                if (cont) { float df = d - tt; a_mse = fmaf(df, df, a_mse); dotc = fmaf(d, tt, dotc); }
            }
        }
        __syncthreads();   // buf[p] published; consumers of previous tile done

        if (!isProd && myrow < rows) {
            // ---- LSE of tile T (runs concurrently with producers filling p^1)
            const __half* row = buf[p] + myrow * NCOLS;
            a_lse += lse_blk_h< 1,  8>(row);
            a_lse += lse_blk_h< 8, 24>(row);
            a_lse += lse_blk_h<24, 31>(row);
            a_lse += lse_blk_h<31, 45>(row);
            a_lse += lse_blk_h<45, 51>(row);
            a_lse += lse_blk_h<51, 53>(row);
            a_lse += lse_blk_h<53, 55>(row);
            a_lse += lse_blk_h<58, 99>(row);
        }
        p ^= 1;
    }

    // ---- block reduce -> double global atomics ----
    float a_dot = (dot0 + dot1) - dotc;
#pragma unroll
    for (int o = 16; o > 0; o >>= 1) {
        a_mse += __shfl_xor_sync(0xFFFFFFFFu, a_mse, o);
        a_dot += __shfl_xor_sync(0xFFFFFFFFu, a_dot, o);
        a_lse += __shfl_xor_sync(0xFFFFFFFFu, a_lse, o);
    }
    if (lane == 0) { wr[0][w] = a_mse; wr[1][w] = a_dot; wr[2][w] = a_lse; }
    __syncthreads();
    if (t == 0) {
        float m = 0.f, d = 0.f, l = 0.f;
#pragma unroll
        for (int k = 0; k < TPB / 32; k++) { m += wr[0][k]; d += wr[1][k]; l += wr[2][k]; }
        atomicAdd(&gz.acc[0], (double)m);
        atomicAdd(&gz.acc[1], (double)d);
        atomicAdd(&gz.acc[2], (double)l);
        __threadfence();
        unsigned tk = atomicAdd(&gz.done[1], 1u);
        s_last = (tk == gridDim.x - 1u) ? 1 : 0;
        if (s_last) {
            while (atomicAdd(&gz.done[2], 0u) < (unsigned)NPREP) __nanosleep(64);
        }
    }
    __syncthreads();

    // ---- last CTA finalizes (double precision, 32 lanes) ----
    if (s_last && t < 32) {
        __threadfence();
        int lane32 = t;
        double mcnt = (lane32 < 10) ? (double)gz.hist[lane32]       : 0.0;
        double fcnt = (lane32 < 10) ? (double)gz.hist[100 + lane32] : 0.0;
#pragma unroll
        for (int o = 16; o > 0; o >>= 1) {
            mcnt += __shfl_xor_sync(0xFFFFFFFFu, mcnt, o);
            fcnt += __shfl_xor_sync(0xFFFFFFFFu, fcnt, o);
        }
        double mc = fmax(mcnt, 1.0), fc = fmax(fcnt, 1.0);
        double kld = 0.0;
#pragma unroll
        for (int k = 0; k < 4; k++) {
            int b = k * 32 + lane32;
            if (b < 100) {
                double p2 = (double)gz.hist[b] / mc;
                double q2 = (double)gz.hist[100 + b] / fc;
                if (p2 > 0.0 && q2 > 0.0) kld += p2 * log(p2 / q2);
            }
        }
#pragma unroll
        for (int o = 16; o > 0; o >>= 1)
            kld += __shfl_xor_sync(0xFFFFFFFFu, kld, o);
        if (lane32 == 0) {
            double mseS = atomicAdd(&gz.acc[0], 0.0);
            double dotS = atomicAdd(&gz.acc[1], 0.0);
            double lseS = atomicAdd(&gz.acc[2], 0.0);
            double fB   = (double)B;
            double mse  = mseS / fB;
            double ce   = (lseS - dotS) / fB;
            double akld = 0.5 * kld;
            out[0] = (float)(0.5 * (mse + ce) + akld);
            out[1] = (float)mse;
            out[2] = (float)ce;
            out[3] = (float)akld;
        }
    }
}

// ---------------- launcher ----------------
extern "C" void kernel_launch(void* const* d_in, const int* in_sizes, int n_in,
                              void* d_out, int out_size) {
    const float* enc = (const float*)d_in[0];   // [B,12]
    const float* dec = (const float*)d_in[1];   // [B,99]
    const float* tru = (const float*)d_in[2];   // [B,99]
    const int B = in_sizes[1] / NCOLS;
    float* out = (float*)d_out;

    void* pz = nullptr;
    cudaGetSymbolAddress(&pz, gz);
    cudaMemsetAsync(pz, 0, sizeof(Zeros), 0);

    cudaFuncSetAttribute(k_fused, cudaFuncAttributePreferredSharedMemoryCarveout, 100);

    k_fused<<<GRID, TPB>>>((const float4*)enc, dec, tru, out, B);
}

// round 10
// speedup vs baseline: 1.0183x; 1.0176x over previous
#include <cuda_runtime.h>
#include <cstdint>

static constexpr int NCOLS = 99;
static constexpr int TPB   = 256;     // 7 consumer warps + 1 producer warp
static constexpr int TILE  = 32;      // rows per stage
static constexpr int NS    = 4;       // pipeline stages
static constexpr int GRID  = 296;     // 2 CTAs/SM, single resident wave
static constexpr int NCONS = 224;     // consumer threads
static constexpr uint32_t STG = TILE * NCOLS * 4;   // 12672 B per array per stage
static constexpr int SMEM_TOTAL = 128 + 2 * NS * (int)STG;   // 101504 B

// ---------------- device scratch (single memset(0), no allocation) ---------
struct Zeros {
    double   acc[3];        // [0]=mse sum, [1]=dot sum, [2]=lse sum
    unsigned hist[200];
    unsigned maxkey[10];
    unsigned cominkey[10];
    unsigned done[3];       // [0] prep minmax sync, [1] finalize ticket, [2] hist done
};
__device__ Zeros gz;

// monotonic float<->uint key
__device__ __forceinline__ unsigned f2key(float f) {
    unsigned u = __float_as_uint(f);
    return (u & 0x80000000u) ? ~u : (u | 0x80000000u);
}
__device__ __forceinline__ float key2f(unsigned k) {
    unsigned u = (k & 0x80000000u) ? (k ^ 0x80000000u) : ~k;
    return __uint_as_float(u);
}

// ---------------- mbarrier / bulk-copy helpers ------------------------------
__device__ __forceinline__ uint32_t s2u(const void* p) {
    return (uint32_t)__cvta_generic_to_shared(p);
}
__device__ __forceinline__ void mbar_init(uint32_t m, uint32_t cnt) {
    asm volatile("mbarrier.init.shared.b64 [%0], %1;" :: "r"(m), "r"(cnt) : "memory");
}
__device__ __forceinline__ void mbar_expect_tx(uint32_t m, uint32_t bytes) {
    asm volatile("mbarrier.arrive.expect_tx.shared.b64 _, [%0], %1;"
                 :: "r"(m), "r"(bytes) : "memory");
}
__device__ __forceinline__ void mbar_arrive(uint32_t m) {
    asm volatile("mbarrier.arrive.shared.b64 _, [%0];" :: "r"(m) : "memory");
}
__device__ __forceinline__ void mbar_wait(uint32_t m, uint32_t parity) {
    asm volatile(
        "{\n\t.reg .pred P;\n\t"
        "WL_%=:\n\t"
        "mbarrier.try_wait.parity.acquire.cta.shared::cta.b64 P, [%0], %1, 0x989680;\n\t"
        "@P bra.uni WD_%=;\n\t"
        "bra.uni WL_%=;\n\t"
        "WD_%=:\n\t}"
        :: "r"(m), "r"(parity) : "memory");
}
__device__ __forceinline__ void bulk_g2s(uint32_t dst, const void* src,
                                         uint32_t bytes, uint32_t mbar) {
    asm volatile(
        "cp.async.bulk.shared::cluster.global.mbarrier::complete_tx::bytes "
        "[%0], [%1], %2, [%3];"
        :: "r"(dst), "l"(src), "r"(bytes), "r"(mbar) : "memory");
}

// ---------------- math helpers ----------------------------------------------
template <int S, int E>
__device__ __forceinline__ float lse_blk(const float* row) {
    float s = 0.f;
#pragma unroll
    for (int c = S; c < E; ++c) s += __expf(row[c]);
    return __logf(s);
}
__device__ __forceinline__ bool quad_rare(int c0) {
    return (c0 == 0) | ((unsigned)(c0 - 52) <= 5u) | (c0 >= 96);
}

// accumulate one float4-pair (from smem), no staging store needed
__device__ __forceinline__ void acc4(
    float4 d, float4 x, int c0,
    float& dot0, float& dot1, float& mse, float& dotc)
{
    dot0 = fmaf(d.x, x.x, dot0);
    dot1 = fmaf(d.y, x.y, dot1);
    dot0 = fmaf(d.z, x.z, dot0);
    dot1 = fmaf(d.w, x.w, dot1);
    if (quad_rare(c0)) {
        float dv[4] = {d.x, d.y, d.z, d.w};
        float xv[4] = {x.x, x.y, x.z, x.w};
        int c = c0;
#pragma unroll
        for (int j = 0; j < 4; j++) {
            bool cont = (c == 0) | ((unsigned)(c - 55) <= 2u);
            if (cont) {
                float df = dv[j] - xv[j];
                mse  = fmaf(df, df, mse);
                dotc = fmaf(dv[j], xv[j], dotc);
            }
            if (++c == NCOLS) c = 0;
        }
    }
}

// ---------------- fused kernel ----------------------------------------------
__global__ void __launch_bounds__(TPB, 2)
k_fused(const float4* __restrict__ e4,
        const float* __restrict__ dec, const float* __restrict__ tru,
        float* __restrict__ out, int B) {
    extern __shared__ char dsm[];              // [128 mbars][NS dec][NS tru]
    __shared__ float s_mn[8][10], s_mx[8][10];
    __shared__ unsigned sh[200];
    __shared__ float smn[10], swid[10];
    __shared__ float wr[3][TPB / 32];
    __shared__ int   s_last;

    const int t = threadIdx.x, lane = t & 31, w = t >> 5;
    const uint32_t mb   = s2u(dsm);
    const uint32_t full0  = mb;                // full[s]  at mb + 8s
    const uint32_t empty0 = mb + 64;           // empty[s] at mb + 64 + 8s
    const uint32_t decS0  = mb + 128;          // dec stage s at +s*STG
    const uint32_t truS0  = mb + 128 + NS * STG;

    if (t == 0) {
#pragma unroll
        for (int s = 0; s < NS; s++) {
            mbar_init(full0  + 8u * s, 1u);
            mbar_init(empty0 + 8u * s, (uint32_t)NCONS);
        }
        asm volatile("fence.proxy.async.shared::cta;" ::: "memory");
    }
    __syncthreads();

    // ================= PREP (all CTAs) =================
    {
        const int stride = GRID * TPB;
        const int gbase  = blockIdx.x * TPB + t;

        float mn[10], mx[10];
        const float INF = __int_as_float(0x7f800000);
#pragma unroll
        for (int i = 0; i < 10; i++) { mn[i] = INF; mx[i] = -INF; }
        for (int r = gbase; r < B; r += 2 * stride) {
            float4 a0 = e4[3*r], b0 = e4[3*r+1], c0 = e4[3*r+2];
            int r1 = r + stride;
            bool ok1 = r1 < B;
            float4 a1, b1, c1;
            if (ok1) { a1 = e4[3*r1]; b1 = e4[3*r1+1]; c1 = e4[3*r1+2]; }
            float v0[10] = {a0.x,a0.y,a0.z,a0.w,b0.x,b0.y,b0.z,b0.w,c0.x,c0.y};
#pragma unroll
            for (int i = 0; i < 10; i++) {
                mn[i] = fminf(mn[i], v0[i]);
                mx[i] = fmaxf(mx[i], v0[i]);
            }
            if (ok1) {
                float v1[10] = {a1.x,a1.y,a1.z,a1.w,b1.x,b1.y,b1.z,b1.w,c1.x,c1.y};
#pragma unroll
                for (int i = 0; i < 10; i++) {
                    mn[i] = fminf(mn[i], v1[i]);
                    mx[i] = fmaxf(mx[i], v1[i]);
                }
            }
        }
#pragma unroll
        for (int i = 0; i < 10; i++) {
#pragma unroll
            for (int o = 16; o > 0; o >>= 1) {
                mn[i] = fminf(mn[i], __shfl_xor_sync(0xFFFFFFFFu, mn[i], o));
                mx[i] = fmaxf(mx[i], __shfl_xor_sync(0xFFFFFFFFu, mx[i], o));
            }
        }
        if (lane == 0) {
#pragma unroll
            for (int i = 0; i < 10; i++) { s_mn[w][i] = mn[i]; s_mx[w][i] = mx[i]; }
        }
        for (int j = t; j < 200; j += TPB) sh[j] = 0u;
        __syncthreads();
        if (t < 10) {
            float m = s_mn[0][t], x = s_mx[0][t];
#pragma unroll
            for (int ww = 1; ww < 8; ww++) { m = fminf(m, s_mn[ww][t]); x = fmaxf(x, s_mx[ww][t]); }
            atomicMax(&gz.cominkey[t], ~f2key(m));
            atomicMax(&gz.maxkey[t],    f2key(x));
        }

        __threadfence();
        __syncthreads();
        if (t == 0) {
            atomicAdd(&gz.done[0], 1u);
            while (atomicAdd(&gz.done[0], 0u) < (unsigned)GRID) __nanosleep(64);
        }
        __syncthreads();
        __threadfence();

        if (t < 10) {
            float m = key2f(~gz.cominkey[t]);
            float x = key2f( gz.maxkey[t]);
            smn[t]  = m;
            swid[t] = fmaxf(x - m, 1e-12f);
        }
        __syncthreads();

        const int B_al = B & ~31;
        for (int r = gbase; r < B_al; r += stride) {
            float4 a = e4[3*r], b = e4[3*r+1], c = e4[3*r+2];
            unsigned base = (c.w == 0.0f) ? 0u : 100u;   // col 11 = sex
            float v[10] = {a.x,a.y,a.z,a.w,b.x,b.y,b.z,b.w,c.x,c.y};
#pragma unroll
            for (int i = 0; i < 10; i++) {
                float tt = (v[i] - smn[i]) / swid[i] * 10.0f;
                int bi = (int)floorf(tt);
                bi = bi < 0 ? 0 : (bi > 9 ? 9 : bi);
                unsigned key = base + (unsigned)(i * 10 + bi);
                unsigned msk = __match_any_sync(0xFFFFFFFFu, key);
                if ((msk & ((1u << lane) - 1u)) == 0u)
                    atomicAdd(&sh[key], (unsigned)__popc(msk));
            }
        }
        for (int r = B_al + gbase; r < B; r += stride) {
            float4 a = e4[3*r], b = e4[3*r+1], c = e4[3*r+2];
            unsigned base = (c.w == 0.0f) ? 0u : 100u;
            float v[10] = {a.x,a.y,a.z,a.w,b.x,b.y,b.z,b.w,c.x,c.y};
#pragma unroll
            for (int i = 0; i < 10; i++) {
                float tt = (v[i] - smn[i]) / swid[i] * 10.0f;
                int bi = (int)floorf(tt);
                bi = bi < 0 ? 0 : (bi > 9 ? 9 : bi);
                atomicAdd(&sh[base + (unsigned)(i * 10 + bi)], 1u);
            }
        }
        __syncthreads();
        for (int j = t; j < 200; j += TPB)
            if (sh[j]) atomicAdd(&gz.hist[j], sh[j]);
        __threadfence();
        __syncthreads();
        if (t == 0) atomicAdd(&gz.done[2], 1u);
    }

    // ================= TILE PIPELINE =================
    // static contiguous tile split (B % TILE == 0 for this problem: 8192 tiles)
    const int NT = B / TILE;
    const int q  = NT / GRID, r_ = NT % GRID;
    const int myN   = q + (blockIdx.x < r_ ? 1 : 0);
    const long start = (long)blockIdx.x * q + min((int)blockIdx.x, r_);

    float dot0 = 0.f, dot1 = 0.f, a_mse = 0.f, dotc = 0.f, a_lse = 0.f;

    if (t == NCONS) {
        // -------- producer (single thread, warp 7) --------
        int ps = 0; uint32_t pp = 1;
        const char* decB = (const char*)dec;
        const char* truB = (const char*)tru;
        for (int n = 0; n < myN; n++) {
            mbar_wait(empty0 + 8u * ps, pp);
            mbar_expect_tx(full0 + 8u * ps, 2u * STG);
            size_t off = (size_t)(start + n) * STG;
            bulk_g2s(decS0 + (uint32_t)ps * STG, decB + off, STG, full0 + 8u * ps);
            bulk_g2s(truS0 + (uint32_t)ps * STG, truB + off, STG, full0 + 8u * ps);
            if (++ps == NS) { ps = 0; pp ^= 1u; }
        }
    } else if (t < NCONS) {
        // -------- consumers (224 threads) --------
        int cs = 0; uint32_t cp = 0;
        const int row   = t >> 1;      // for LSE (t < 64)
        const int halfO = t & 1;
        for (int n = 0; n < myN; n++) {
            mbar_wait(full0 + 8u * cs, cp);
            const float*  D  = (const float*)(dsm + 128 + cs * STG);
            const float*  X  = (const float*)(dsm + 128 + NS * STG + cs * STG);
            const float4* D4 = (const float4*)D;
            const float4* X4 = (const float4*)X;

            // phase A: elementwise dot / mse over the stage (792 float4)
            for (int i4 = t; i4 < (TILE * NCOLS) / 4; i4 += NCONS) {
                int c0 = (4 * i4) % NCOLS;
                acc4(D4[i4], X4[i4], c0, dot0, dot1, a_mse, dotc);
            }
            // phase B: LSE, 2 threads per row
            if (t < 2 * TILE) {
                const float* rp = D + row * NCOLS;
                if (halfO == 0) {
                    a_lse += lse_blk< 1,  8>(rp);
                    a_lse += lse_blk< 8, 24>(rp);
                    a_lse += lse_blk<24, 31>(rp);
                    a_lse += lse_blk<31, 45>(rp);
                } else {
                    a_lse += lse_blk<45, 51>(rp);
                    a_lse += lse_blk<51, 53>(rp);
                    a_lse += lse_blk<53, 55>(rp);
                    a_lse += lse_blk<58, 99>(rp);
                }
            }
            mbar_arrive(empty0 + 8u * cs);
            if (++cs == NS) { cs = 0; cp ^= 1u; }
        }
    }

    // ---- block reduce -> double global atomics ----
    float a_dot = (dot0 + dot1) - dotc;
#pragma unroll
    for (int o = 16; o > 0; o >>= 1) {
        a_mse += __shfl_xor_sync(0xFFFFFFFFu, a_mse, o);
        a_dot += __shfl_xor_sync(0xFFFFFFFFu, a_dot, o);
        a_lse += __shfl_xor_sync(0xFFFFFFFFu, a_lse, o);
    }
    if (lane == 0) { wr[0][w] = a_mse; wr[1][w] = a_dot; wr[2][w] = a_lse; }
    __syncthreads();
    if (t == 0) {
        float m = 0.f, d = 0.f, l = 0.f;
#pragma unroll
        for (int k = 0; k < TPB / 32; k++) { m += wr[0][k]; d += wr[1][k]; l += wr[2][k]; }
        atomicAdd(&gz.acc[0], (double)m);
        atomicAdd(&gz.acc[1], (double)d);
        atomicAdd(&gz.acc[2], (double)l);
        __threadfence();
        unsigned tk = atomicAdd(&gz.done[1], 1u);
        s_last = (tk == (unsigned)(GRID - 1)) ? 1 : 0;
        if (s_last) {
            while (atomicAdd(&gz.done[2], 0u) < (unsigned)GRID) __nanosleep(64);
        }
    }
    __syncthreads();

    // ---- last CTA finalizes (double precision, 32 lanes) ----
    if (s_last && t < 32) {
        __threadfence();
        int lane32 = t;
        double mcnt = (lane32 < 10) ? (double)gz.hist[lane32]       : 0.0;
        double fcnt = (lane32 < 10) ? (double)gz.hist[100 + lane32] : 0.0;
#pragma unroll
        for (int o = 16; o > 0; o >>= 1) {
            mcnt += __shfl_xor_sync(0xFFFFFFFFu, mcnt, o);
            fcnt += __shfl_xor_sync(0xFFFFFFFFu, fcnt, o);
        }
        double mc = fmax(mcnt, 1.0), fc = fmax(fcnt, 1.0);
        double kld = 0.0;
#pragma unroll
        for (int k = 0; k < 4; k++) {
            int b = k * 32 + lane32;
            if (b < 100) {
                double p2 = (double)gz.hist[b] / mc;
                double q2 = (double)gz.hist[100 + b] / fc;
                if (p2 > 0.0 && q2 > 0.0) kld += p2 * log(p2 / q2);
            }
        }
#pragma unroll
        for (int o = 16; o > 0; o >>= 1)
            kld += __shfl_xor_sync(0xFFFFFFFFu, kld, o);
        if (lane32 == 0) {
            double mseS = atomicAdd(&gz.acc[0], 0.0);
            double dotS = atomicAdd(&gz.acc[1], 0.0);
            double lseS = atomicAdd(&gz.acc[2], 0.0);
            double fB   = (double)B;
            double mse  = mseS / fB;
            double ce   = (lseS - dotS) / fB;
            double akld = 0.5 * kld;
            out[0] = (float)(0.5 * (mse + ce) + akld);
            out[1] = (float)mse;
            out[2] = (float)ce;
            out[3] = (float)akld;
        }
    }
}

// ---------------- launcher ----------------
extern "C" void kernel_launch(void* const* d_in, const int* in_sizes, int n_in,
                              void* d_out, int out_size) {
    const float* enc = (const float*)d_in[0];   // [B,12]
    const float* dec = (const float*)d_in[1];   // [B,99]
    const float* tru = (const float*)d_in[2];   // [B,99]
    const int B = in_sizes[1] / NCOLS;
    float* out = (float*)d_out;

    void* pz = nullptr;
    cudaGetSymbolAddress(&pz, gz);
    cudaMemsetAsync(pz, 0, sizeof(Zeros), 0);

    cudaFuncSetAttribute(k_fused, cudaFuncAttributeMaxDynamicSharedMemorySize, SMEM_TOTAL);

    k_fused<<<GRID, TPB, SMEM_TOTAL>>>((const float4*)enc, dec, tru, out, B);
}